// round 15
// baseline (speedup 1.0000x reference)
#include <cuda_runtime.h>
#include <cuda_fp16.h>
#include <cstdint>
#include <cstddef>

#define NN 50000
#define EE 850000
#define HH 4

// ---------------- scratch (static device globals; no runtime alloc) ----------
__device__ __half g_hh1[(size_t)NN * 256];    // layer-1 h (fp16 gather table)
__device__ __half g_hh2[(size_t)NN * 256];    // layer-2 h
__device__ float g_el1[NN * HH];
__device__ float g_er1[NN * HH];
__device__ float g_el2[NN * HH];
__device__ float g_er2[NN * HH];
__device__ __align__(16) int g_indeg[NN];
__device__ __align__(16) int g_off[NN + 4];
__device__ __align__(16) int g_cur[NN];
__device__ int   g_csrc[EE];                  // CSR payload: src node id
__device__ __half g_Ah[(size_t)NN * 256];     // layer-1 GEMM input (fp16)
__device__ __half g_Ah2[(size_t)NN * 256];    // layer-2 GEMM input (fp16)
__device__ __half g_Wt1[256 * 256];           // W1 fp16, transposed [n][k]
__device__ __half g_Wt2[256 * 256];           // W2 fp16, transposed [n][k]

// ---------------- PTX helpers ----------------
__device__ __forceinline__ uint32_t smem_u32(const void* p) {
    uint32_t a;
    asm("{ .reg .u64 t; cvta.to.shared.u64 t, %1; cvt.u32.u64 %0, t; }"
        : "=r"(a) : "l"(p));
    return a;
}
#define CP_ASYNC16(dst, src) \
    asm volatile("cp.async.cg.shared.global [%0], [%1], 16;" :: "r"(dst), "l"(src))
#define CP_COMMIT() asm volatile("cp.async.commit_group;" ::: "memory")
#define CP_WAIT(n)  asm volatile("cp.async.wait_group %0;" :: "n"(n) : "memory")

__device__ __forceinline__ void mma_f16(float* c, const uint32_t* a,
                                        uint32_t b0, uint32_t b1) {
    asm volatile(
        "mma.sync.aligned.m16n8k16.row.col.f32.f16.f16.f32 "
        "{%0,%1,%2,%3}, {%4,%5,%6,%7}, {%8,%9}, {%0,%1,%2,%3};"
        : "+f"(c[0]), "+f"(c[1]), "+f"(c[2]), "+f"(c[3])
        : "r"(a[0]), "r"(a[1]), "r"(a[2]), "r"(a[3]), "r"(b0), "r"(b1));
}
__device__ __forceinline__ void ldm_x4(uint32_t* r, uint32_t addr) {
    asm volatile(
        "ldmatrix.sync.aligned.m8n8.x4.shared.b16 {%0,%1,%2,%3}, [%4];"
        : "=r"(r[0]), "=r"(r[1]), "=r"(r[2]), "=r"(r[3]) : "r"(addr));
}

// ---------------- CSR build ----------------
__global__ void zero_indeg_kernel() {
    int i = blockIdx.x * blockDim.x + threadIdx.x;
    if (i < NN) g_indeg[i] = 0;
}

__global__ void csr_count_kernel(const int* __restrict__ dst, int E) {
    int e = blockIdx.x * blockDim.x + threadIdx.x;
    if (e < E) atomicAdd(&g_indeg[dst[e]], 1);
}

__global__ void scan_kernel() {
    __shared__ int warp_sums[32];
    __shared__ int s_carry;
    int tid = threadIdx.x;
    int lane = tid & 31, wid = tid >> 5;
    if (tid == 0) s_carry = 0;
    __syncthreads();
    const int NQ = NN / 4;
    for (int base = 0; base < NQ; base += 1024) {
        int idx = base + tid;
        int4 v = make_int4(0, 0, 0, 0);
        if (idx < NQ) v = ((const int4*)g_indeg)[idx];
        int tot = v.x + v.y + v.z + v.w;
        int x = tot;
        #pragma unroll
        for (int o = 1; o < 32; o <<= 1) {
            int t = __shfl_up_sync(0xffffffffu, x, o);
            if (lane >= o) x += t;
        }
        if (lane == 31) warp_sums[wid] = x;
        __syncthreads();
        if (wid == 0) {
            int ws = warp_sums[lane];
            #pragma unroll
            for (int o = 1; o < 32; o <<= 1) {
                int t = __shfl_up_sync(0xffffffffu, ws, o);
                if (lane >= o) ws += t;
            }
            warp_sums[lane] = ws;
        }
        __syncthreads();
        int warp_excl = (wid == 0) ? 0 : warp_sums[wid - 1];
        int excl = x - tot + warp_excl + s_carry;
        if (idx < NQ) {
            int4 o;
            o.x = excl;
            o.y = o.x + v.x;
            o.z = o.y + v.y;
            o.w = o.z + v.z;
            ((int4*)g_off)[idx] = o;
            ((int4*)g_cur)[idx] = o;
        }
        __syncthreads();
        if (tid == 0) s_carry += warp_sums[31];
        __syncthreads();
    }
    if (threadIdx.x == 0) g_off[NN] = s_carry;
}

__global__ void csr_scatter_kernel(const int* __restrict__ dst,
                                   const int* __restrict__ src, int E) {
    int e = blockIdx.x * blockDim.x + threadIdx.x;
    if (e < E) {
        int p = atomicAdd(&g_cur[dst[e]], 1);
        g_csrc[p] = src[e];
    }
}

// ---------------- splits ----------------
__global__ void wsplit_kernel(const float* __restrict__ W, __half* __restrict__ Wt) {
    int idx = blockIdx.x * 256 + threadIdx.x;
    int k = idx >> 8, n = idx & 255;
    Wt[n * 256 + k] = __float2half_rn(W[k * 256 + n]);
}

__global__ void asplit_kernel(const float* __restrict__ X, size_t elemOff) {
    size_t i = elemOff + ((size_t)blockIdx.x * 256 + threadIdx.x) * 2;
    float2 v = *(const float2*)(X + i);
    *(__half2*)(g_Ah + i) = __floats2half2_rn(v.x, v.y);
}

// --------- fp16 mma.sync GEMM (2-stage, column-half) + fused attn epilogue ---
// Computes h[:, colBase..colBase+128) = A @ Wt[colBase..colBase+128)^T and
// el/er for heads colBase/64 + {0,1}.
#define SA 40
#define ATILE (128 * SA)
#define BUFB (2 * ATILE * 2)
#define GEMM_SMEM (2 * BUFB)

__global__ __launch_bounds__(256) void gemm_mma_kernel(
    const __half* __restrict__ A, const __half* __restrict__ Wt,
    const float* __restrict__ al, const float* __restrict__ ar,
    __half* __restrict__ hh_out, float* __restrict__ el_out,
    float* __restrict__ er_out, int colBase, int nrows)
{
    extern __shared__ __half sm[];
    int tid = threadIdx.x;
    int lane = tid & 31;
    int wid = tid >> 5;
    int wm = wid & 3, wn = wid >> 2;
    int g = lane >> 2, t = lane & 3;
    int rowBase = blockIdx.x * 128;
    int nbase = colBase;

    uint32_t sb = smem_u32(sm);

    uint32_t aOff = (uint32_t)(((wm * 32 + (lane & 15)) * SA + ((lane >> 4) << 3)) * 2);
    uint32_t bOff = (uint32_t)(((wn * 64 + ((lane >> 4) << 3) + (lane & 7)) * SA +
                                (((lane >> 3) & 1) << 3)) * 2);

    float acc[2][8][4];
    #pragma unroll
    for (int mt = 0; mt < 2; mt++)
        #pragma unroll
        for (int nt = 0; nt < 8; nt++)
            #pragma unroll
            for (int q = 0; q < 4; q++) acc[mt][nt][q] = 0.f;

    #define STAGE(buf, k0)                                                        \
    do {                                                                          \
        uint32_t base = sb + (uint32_t)(buf) * BUFB;                              \
        _Pragma("unroll")                                                         \
        for (int p = 0; p < 2; p++) {                                             \
            int c = tid + p * 256;                                                \
            int r = c >> 2, j = c & 3;                                            \
            uint32_t so = (uint32_t)(r * (SA * 2) + j * 16);                      \
            int arow = rowBase + r;                                               \
            if (arow < nrows)                                                     \
                CP_ASYNC16(base + so, A + (size_t)arow * 256 + (k0) + j * 8);     \
            CP_ASYNC16(base + ATILE * 2 + so,                                     \
                       Wt + (size_t)(nbase + r) * 256 + (k0) + j * 8);            \
        }                                                                         \
        CP_COMMIT();                                                              \
    } while (0)

    STAGE(0, 0);

    #pragma unroll
    for (int kt = 0; kt < 8; kt++) {
        if (kt < 7) STAGE((kt + 1) & 1, (kt + 1) * 32);
        if (kt < 7) { CP_WAIT(1); } else { CP_WAIT(0); }
        __syncthreads();

        uint32_t bufb = sb + (uint32_t)(kt & 1) * BUFB;
        uint32_t aP = bufb + aOff;
        uint32_t bP = bufb + ATILE * 2 + bOff;

        #pragma unroll
        for (int kk = 0; kk < 2; kk++) {
            uint32_t ksb = (uint32_t)(kk * 32);
            uint32_t ah[2][4];
            #pragma unroll
            for (int mt = 0; mt < 2; mt++)
                ldm_x4(ah[mt], aP + (uint32_t)(mt * 16 * SA * 2) + ksb);
            #pragma unroll
            for (int p = 0; p < 4; p++) {
                uint32_t bh[4];
                ldm_x4(bh, bP + (uint32_t)(p * 16 * SA * 2) + ksb);
                #pragma unroll
                for (int sub = 0; sub < 2; sub++) {
                    int nt = p * 2 + sub;
                    #pragma unroll
                    for (int mt = 0; mt < 2; mt++)
                        mma_f16(acc[mt][nt], ah[mt], bh[2 * sub], bh[2 * sub + 1]);
                }
            }
        }
        __syncthreads();
    }

    // ---- epilogue: write h fp16 + fused el/er ----
    int head = (colBase >> 6) + wn;
    float2 alv[8], arv[8];
    #pragma unroll
    for (int nt = 0; nt < 8; nt++) {
        int d = nt * 8 + 2 * t;
        alv[nt] = *(const float2*)(al + head * 64 + d);
        arv[nt] = *(const float2*)(ar + head * 64 + d);
    }

    #pragma unroll
    for (int mt = 0; mt < 2; mt++) {
        int r0 = rowBase + wm * 32 + mt * 16 + g;
        int r1 = r0 + 8;
        float el0 = 0.f, er0 = 0.f, el1 = 0.f, er1 = 0.f;
        #pragma unroll
        for (int nt = 0; nt < 8; nt++) {
            int col = colBase + wn * 64 + nt * 8 + 2 * t;
            if (r0 < nrows)
                *(__half2*)(hh_out + (size_t)r0 * 256 + col) =
                    __floats2half2_rn(acc[mt][nt][0], acc[mt][nt][1]);
            if (r1 < nrows)
                *(__half2*)(hh_out + (size_t)r1 * 256 + col) =
                    __floats2half2_rn(acc[mt][nt][2], acc[mt][nt][3]);
            el0 += acc[mt][nt][0] * alv[nt].x + acc[mt][nt][1] * alv[nt].y;
            er0 += acc[mt][nt][0] * arv[nt].x + acc[mt][nt][1] * arv[nt].y;
            el1 += acc[mt][nt][2] * alv[nt].x + acc[mt][nt][3] * alv[nt].y;
            er1 += acc[mt][nt][2] * arv[nt].x + acc[mt][nt][3] * arv[nt].y;
        }
        #pragma unroll
        for (int o = 1; o < 4; o <<= 1) {
            el0 += __shfl_xor_sync(0xffffffffu, el0, o);
            er0 += __shfl_xor_sync(0xffffffffu, er0, o);
            el1 += __shfl_xor_sync(0xffffffffu, el1, o);
            er1 += __shfl_xor_sync(0xffffffffu, er1, o);
        }
        if (t == 0) {
            if (r0 < nrows) { el_out[r0 * 4 + head] = el0; er_out[r0 * 4 + head] = er0; }
            if (r1 < nrows) { el_out[r1 * 4 + head] = el1; er_out[r1 * 4 + head] = er1; }
        }
    }
}

// ---- warp-per-node edge-softmax + aggregation for ONE head-pair (hp=0/1) ----
// lane covers 4 features at col = hp*128 + lane*4; sub-head = lane>>4.
__global__ __launch_bounds__(256) void aggregate_kernel(
    const __half* __restrict__ hh, const float* __restrict__ el,
    const float* __restrict__ er, const float* __restrict__ bias,
    float* __restrict__ outf, __half* __restrict__ aout, int hp)
{
    __shared__ float s_w[8][32][2];
    __shared__ int   s_s[8][32];
    int w = threadIdx.x >> 5, lane = threadIdx.x & 31;
    int n = blockIdx.x * 8 + w;          // NN = 6250*8, exact
    int beg = g_off[n], end = g_off[n + 1];
    int sh = lane >> 4;
    int col = hp * 128 + lane * 4;

    float2 rn = ((const float2*)er)[n * 2 + hp];
    float acc[4] = {0.f, 0.f, 0.f, 0.f};
    float den = 0.f;
    const __half* htab = hh + col;

    for (int base = beg; base < end; base += 32) {
        int m = end - base;
        if (m > 32) m = 32;
        if (lane < m) {
            int s = g_csrc[base + lane];
            float2 l = ((const float2*)el)[s * 2 + hp];
            float e0 = l.x + rn.x; e0 = (e0 > 0.f) ? e0 : 0.2f * e0;
            float e1 = l.y + rn.y; e1 = (e1 > 0.f) ? e1 : 0.2f * e1;
            s_s[w][lane] = s;
            s_w[w][lane][0] = __expf(e0);
            s_w[w][lane][1] = __expf(e1);
        }
        __syncwarp();
        #define ACC2(hv, a)                                                       \
        do {                                                                      \
            float2 f0 = __half22float2(*(const __half2*)&(hv).x);                 \
            float2 f1 = __half22float2(*(const __half2*)&(hv).y);                 \
            acc[0] += (a) * f0.x; acc[1] += (a) * f0.y;                           \
            acc[2] += (a) * f1.x; acc[3] += (a) * f1.y;                           \
        } while (0)
        int j = 0;
        for (; j + 4 <= m; j += 4) {
            int   s0 = s_s[w][j],     s1 = s_s[w][j + 1];
            int   s2 = s_s[w][j + 2], s3 = s_s[w][j + 3];
            float a0 = s_w[w][j][sh],     a1 = s_w[w][j + 1][sh];
            float a2 = s_w[w][j + 2][sh], a3 = s_w[w][j + 3][sh];
            uint2 h0 = *(const uint2*)(htab + (size_t)s0 * 256);
            uint2 h1 = *(const uint2*)(htab + (size_t)s1 * 256);
            uint2 h2 = *(const uint2*)(htab + (size_t)s2 * 256);
            uint2 h3 = *(const uint2*)(htab + (size_t)s3 * 256);
            ACC2(h0, a0);
            ACC2(h1, a1);
            ACC2(h2, a2);
            ACC2(h3, a3);
            den += (a0 + a1) + (a2 + a3);
        }
        for (; j < m; j++) {
            int s0 = s_s[w][j];
            float a0 = s_w[w][j][sh];
            uint2 h0 = *(const uint2*)(htab + (size_t)s0 * 256);
            ACC2(h0, a0);
            den += a0;
        }
        __syncwarp();
    }

    float inv = 1.f / den;
    float4 b = *(const float4*)(bias + col);
    float v0 = fmaxf(acc[0] * inv + b.x, 0.f);
    float v1 = fmaxf(acc[1] * inv + b.y, 0.f);
    float v2 = fmaxf(acc[2] * inv + b.z, 0.f);
    float v3 = fmaxf(acc[3] * inv + b.w, 0.f);
    size_t oi = (size_t)n * 256 + col;
    if (aout) {
        uint2 pk;
        *(__half2*)&pk.x = __floats2half2_rn(v0, v1);
        *(__half2*)&pk.y = __floats2half2_rn(v2, v3);
        *(uint2*)(aout + oi) = pk;
    } else {
        *(float4*)(outf + oi) = make_float4(v0, v1, v2, v3);
    }
}

// ---------------- launch ----------------
extern "C" void kernel_launch(void* const* d_in, const int* in_sizes, int n_in,
                              void* d_out, int out_size)
{
    const float* feat = (const float*)d_in[0];
    const int*   src  = (const int*)d_in[1];
    const int*   dst  = (const int*)d_in[2];
    const float* W1   = (const float*)d_in[3];
    const float* al1  = (const float*)d_in[4];
    const float* ar1  = (const float*)d_in[5];
    const float* b1   = (const float*)d_in[6];
    const float* W2   = (const float*)d_in[7];
    const float* al2  = (const float*)d_in[8];
    const float* ar2  = (const float*)d_in[9];
    const float* b2   = (const float*)d_in[10];
    float* out = (float*)d_out;
    int E = in_sizes[1];

    void* p;
    cudaGetSymbolAddress(&p, g_Ah);  __half* ah  = (__half*)p;
    cudaGetSymbolAddress(&p, g_Ah2); __half* ah2 = (__half*)p;
    cudaGetSymbolAddress(&p, g_Wt1); __half* wt1 = (__half*)p;
    cudaGetSymbolAddress(&p, g_Wt2); __half* wt2 = (__half*)p;
    cudaGetSymbolAddress(&p, g_hh1); __half* hh1 = (__half*)p;
    cudaGetSymbolAddress(&p, g_hh2); __half* hh2 = (__half*)p;
    cudaGetSymbolAddress(&p, g_el1); float* el1 = (float*)p;
    cudaGetSymbolAddress(&p, g_er1); float* er1 = (float*)p;
    cudaGetSymbolAddress(&p, g_el2); float* el2 = (float*)p;
    cudaGetSymbolAddress(&p, g_er2); float* er2 = (float*)p;

    static cudaStream_t s2 = nullptr, s3 = nullptr;
    static cudaEvent_t evFork = nullptr, evJoin = nullptr, evAsb = nullptr;
    static cudaEvent_t evG1y0 = nullptr, evA101 = nullptr;
    static cudaEvent_t evG2y0 = nullptr, evA201 = nullptr;
    static int init_done = 0;
    if (!init_done) {
        cudaFuncSetAttribute(gemm_mma_kernel,
                             cudaFuncAttributeMaxDynamicSharedMemorySize, GEMM_SMEM);
        cudaStreamCreateWithFlags(&s2, cudaStreamNonBlocking);
        cudaStreamCreateWithFlags(&s3, cudaStreamNonBlocking);
        cudaEventCreateWithFlags(&evFork, cudaEventDisableTiming);
        cudaEventCreateWithFlags(&evJoin, cudaEventDisableTiming);
        cudaEventCreateWithFlags(&evAsb, cudaEventDisableTiming);
        cudaEventCreateWithFlags(&evG1y0, cudaEventDisableTiming);
        cudaEventCreateWithFlags(&evA101, cudaEventDisableTiming);
        cudaEventCreateWithFlags(&evG2y0, cudaEventDisableTiming);
        cudaEventCreateWithFlags(&evA201, cudaEventDisableTiming);
        init_done = 1;
    }

    int egrid = (E + 255) / 256;
    int ngrid = (NN + 255) / 256;
    int ggrid = (NN + 127) / 128;               // 391
    int agrid = NN / 8;                          // 6250
    const int HALF_ELEMS = NN * 128;             // elements per asplit half
    const int ASPLIT_BLK = HALF_ELEMS / 512;     // 12500 blocks

    cudaEventRecord(evFork, 0);
    // s2: CSR build (overlaps splits + GEMM-1 y0)
    cudaStreamWaitEvent(s2, evFork, 0);
    zero_indeg_kernel<<<ngrid, 256, 0, s2>>>();
    csr_count_kernel<<<egrid, 256, 0, s2>>>(dst, E);
    scan_kernel<<<1, 1024, 0, s2>>>();
    csr_scatter_kernel<<<egrid, 256, 0, s2>>>(dst, src, E);
    cudaEventRecord(evJoin, s2);

    // s3: second half of feature convert
    cudaStreamWaitEvent(s3, evFork, 0);
    asplit_kernel<<<ASPLIT_BLK, 256, 0, s3>>>(feat, (size_t)HALF_ELEMS);
    cudaEventRecord(evAsb, s3);

    // s0: weight tables + first-half convert + gemm1 y0
    wsplit_kernel<<<256, 256>>>(W1, wt1);
    wsplit_kernel<<<256, 256>>>(W2, wt2);
    asplit_kernel<<<ASPLIT_BLK, 256>>>(feat, 0);
    cudaStreamWaitEvent(0, evAsb, 0);
    gemm_mma_kernel<<<ggrid, 256, GEMM_SMEM>>>(ah, wt1, al1, ar1,
                                               hh1, el1, er1, 0, NN);
    cudaEventRecord(evG1y0, 0);

    // s2: agg1 heads 0-1 (needs CSR in-stream + gemm1 y0) ∥ gemm1 y1 on s0
    cudaStreamWaitEvent(s2, evG1y0, 0);
    aggregate_kernel<<<agrid, 256, 0, s2>>>(hh1, el1, er1, b1, nullptr, ah2, 0);
    cudaEventRecord(evA101, s2);

    // s0: gemm1 y1, then agg1 heads 2-3
    gemm_mma_kernel<<<ggrid, 256, GEMM_SMEM>>>(ah, wt1, al1, ar1,
                                               hh1, el1, er1, 128, NN);
    cudaStreamWaitEvent(0, evJoin, 0);
    aggregate_kernel<<<agrid, 256>>>(hh1, el1, er1, b1, nullptr, ah2, 1);

    // s0: gemm2 y0 (needs full ah2: agg1_23 in-stream + agg1_01 via event)
    cudaStreamWaitEvent(0, evA101, 0);
    gemm_mma_kernel<<<ggrid, 256, GEMM_SMEM>>>(ah2, wt2, al2, ar2,
                                               hh2, el2, er2, 0, NN);
    cudaEventRecord(evG2y0, 0);

    // s2: agg2 heads 0-1 ∥ gemm2 y1 on s0
    cudaStreamWaitEvent(s2, evG2y0, 0);
    aggregate_kernel<<<agrid, 256, 0, s2>>>(hh2, el2, er2, b2, out, nullptr, 0);
    cudaEventRecord(evA201, s2);

    // s0: gemm2 y1 then agg2 heads 2-3; join s2 at the end
    gemm_mma_kernel<<<ggrid, 256, GEMM_SMEM>>>(ah2, wt2, al2, ar2,
                                               hh2, el2, er2, 128, NN);
    aggregate_kernel<<<agrid, 256>>>(hh2, el2, er2, b2, out, nullptr, 1);
    cudaStreamWaitEvent(0, evA201, 0);
}

// round 16
// speedup vs baseline: 1.1885x; 1.1885x over previous
#include <cuda_runtime.h>
#include <cuda_fp16.h>
#include <cstdint>
#include <cstddef>

#define NN 50000
#define EE 850000
#define HH 4
#define SPLIT 16640                     // = 130*128 = 2080*8  (~NN/3, overlap-optimal)

// ---------------- scratch (static device globals; no runtime alloc) ----------
__device__ __half g_hh1[(size_t)NN * 256];    // layer-1 h (fp16 gather table)
__device__ __half g_hh2[(size_t)NN * 256];    // layer-2 h
__device__ float g_el1[NN * HH];
__device__ float g_er1[NN * HH];
__device__ float g_el2[NN * HH];
__device__ float g_er2[NN * HH];
__device__ __align__(16) int g_indeg[NN];
__device__ __align__(16) int g_off[NN + 4];
__device__ __align__(16) int g_cur[NN];
__device__ int   g_csrc[EE];                  // CSR payload: src node id
__device__ __half g_Ah[(size_t)NN * 256];     // GEMM input (fp16)
__device__ __half g_Wt1[256 * 256];           // W1 fp16, transposed [n][k]
__device__ __half g_Wt2[256 * 256];           // W2 fp16, transposed [n][k]

// ---------------- PTX helpers ----------------
__device__ __forceinline__ uint32_t smem_u32(const void* p) {
    uint32_t a;
    asm("{ .reg .u64 t; cvta.to.shared.u64 t, %1; cvt.u32.u64 %0, t; }"
        : "=r"(a) : "l"(p));
    return a;
}
#define CP_ASYNC16(dst, src) \
    asm volatile("cp.async.cg.shared.global [%0], [%1], 16;" :: "r"(dst), "l"(src))
#define CP_COMMIT() asm volatile("cp.async.commit_group;" ::: "memory")
#define CP_WAIT(n)  asm volatile("cp.async.wait_group %0;" :: "n"(n) : "memory")

__device__ __forceinline__ void mma_f16(float* c, const uint32_t* a,
                                        uint32_t b0, uint32_t b1) {
    asm volatile(
        "mma.sync.aligned.m16n8k16.row.col.f32.f16.f16.f32 "
        "{%0,%1,%2,%3}, {%4,%5,%6,%7}, {%8,%9}, {%0,%1,%2,%3};"
        : "+f"(c[0]), "+f"(c[1]), "+f"(c[2]), "+f"(c[3])
        : "r"(a[0]), "r"(a[1]), "r"(a[2]), "r"(a[3]), "r"(b0), "r"(b1));
}
__device__ __forceinline__ void ldm_x4(uint32_t* r, uint32_t addr) {
    asm volatile(
        "ldmatrix.sync.aligned.m8n8.x4.shared.b16 {%0,%1,%2,%3}, [%4];"
        : "=r"(r[0]), "=r"(r[1]), "=r"(r[2]), "=r"(r[3]) : "r"(addr));
}

// ---------------- CSR build ----------------
__global__ void zero_indeg_kernel() {
    int i = blockIdx.x * blockDim.x + threadIdx.x;
    if (i < NN) g_indeg[i] = 0;
}

__global__ void csr_count_kernel(const int* __restrict__ dst, int E) {
    int e = blockIdx.x * blockDim.x + threadIdx.x;
    if (e < E) atomicAdd(&g_indeg[dst[e]], 1);
}

__global__ void scan_kernel() {
    __shared__ int warp_sums[32];
    __shared__ int s_carry;
    int tid = threadIdx.x;
    int lane = tid & 31, wid = tid >> 5;
    if (tid == 0) s_carry = 0;
    __syncthreads();
    const int NQ = NN / 4;
    for (int base = 0; base < NQ; base += 1024) {
        int idx = base + tid;
        int4 v = make_int4(0, 0, 0, 0);
        if (idx < NQ) v = ((const int4*)g_indeg)[idx];
        int tot = v.x + v.y + v.z + v.w;
        int x = tot;
        #pragma unroll
        for (int o = 1; o < 32; o <<= 1) {
            int t = __shfl_up_sync(0xffffffffu, x, o);
            if (lane >= o) x += t;
        }
        if (lane == 31) warp_sums[wid] = x;
        __syncthreads();
        if (wid == 0) {
            int ws = warp_sums[lane];
            #pragma unroll
            for (int o = 1; o < 32; o <<= 1) {
                int t = __shfl_up_sync(0xffffffffu, ws, o);
                if (lane >= o) ws += t;
            }
            warp_sums[lane] = ws;
        }
        __syncthreads();
        int warp_excl = (wid == 0) ? 0 : warp_sums[wid - 1];
        int excl = x - tot + warp_excl + s_carry;
        if (idx < NQ) {
            int4 o;
            o.x = excl;
            o.y = o.x + v.x;
            o.z = o.y + v.y;
            o.w = o.z + v.z;
            ((int4*)g_off)[idx] = o;
            ((int4*)g_cur)[idx] = o;
        }
        __syncthreads();
        if (tid == 0) s_carry += warp_sums[31];
        __syncthreads();
    }
    if (threadIdx.x == 0) g_off[NN] = s_carry;
}

__global__ void csr_scatter_kernel(const int* __restrict__ dst,
                                   const int* __restrict__ src, int E) {
    int e = blockIdx.x * blockDim.x + threadIdx.x;
    if (e < E) {
        int p = atomicAdd(&g_cur[dst[e]], 1);
        g_csrc[p] = src[e];
    }
}

// ---------------- splits ----------------
__global__ void wsplit_kernel(const float* __restrict__ W, __half* __restrict__ Wt) {
    int idx = blockIdx.x * 256 + threadIdx.x;
    int k = idx >> 8, n = idx & 255;
    Wt[n * 256 + k] = __float2half_rn(W[k * 256 + n]);
}

__global__ void asplit_kernel(const float* __restrict__ X, size_t elemOff) {
    size_t i = elemOff + ((size_t)blockIdx.x * 256 + threadIdx.x) * 2;
    float2 v = *(const float2*)(X + i);
    *(__half2*)(g_Ah + i) = __floats2half2_rn(v.x, v.y);
}

// --------- fp16 mma.sync GEMM (2-stage cp.async) + fused attn epilogue -------
#define SA 40
#define ATILE (128 * SA)
#define BUFB (2 * ATILE * 2)
#define GEMM_SMEM (2 * BUFB)

__global__ __launch_bounds__(256) void gemm_mma_kernel(
    const __half* __restrict__ A, const __half* __restrict__ Wt,
    const float* __restrict__ al, const float* __restrict__ ar,
    __half* __restrict__ hh_out, float* __restrict__ el_out,
    float* __restrict__ er_out, int rowOff, int nrows)
{
    extern __shared__ __half sm[];
    int tid = threadIdx.x;
    int lane = tid & 31;
    int wid = tid >> 5;
    int wm = wid & 3, wn = wid >> 2;
    int g = lane >> 2, t = lane & 3;
    int rowBase = rowOff + blockIdx.x * 128;
    int nbase = blockIdx.y * 128;

    uint32_t sb = smem_u32(sm);

    uint32_t aOff = (uint32_t)(((wm * 32 + (lane & 15)) * SA + ((lane >> 4) << 3)) * 2);
    uint32_t bOff = (uint32_t)(((wn * 64 + ((lane >> 4) << 3) + (lane & 7)) * SA +
                                (((lane >> 3) & 1) << 3)) * 2);

    float acc[2][8][4];
    #pragma unroll
    for (int mt = 0; mt < 2; mt++)
        #pragma unroll
        for (int nt = 0; nt < 8; nt++)
            #pragma unroll
            for (int q = 0; q < 4; q++) acc[mt][nt][q] = 0.f;

    #define STAGE(buf, k0)                                                        \
    do {                                                                          \
        uint32_t base = sb + (uint32_t)(buf) * BUFB;                              \
        _Pragma("unroll")                                                         \
        for (int p = 0; p < 2; p++) {                                             \
            int c = tid + p * 256;                                                \
            int r = c >> 2, j = c & 3;                                            \
            uint32_t so = (uint32_t)(r * (SA * 2) + j * 16);                      \
            int arow = rowBase + r;                                               \
            if (arow < nrows)                                                     \
                CP_ASYNC16(base + so, A + (size_t)arow * 256 + (k0) + j * 8);     \
            CP_ASYNC16(base + ATILE * 2 + so,                                     \
                       Wt + (size_t)(nbase + r) * 256 + (k0) + j * 8);            \
        }                                                                         \
        CP_COMMIT();                                                              \
    } while (0)

    STAGE(0, 0);

    #pragma unroll
    for (int kt = 0; kt < 8; kt++) {
        if (kt < 7) STAGE((kt + 1) & 1, (kt + 1) * 32);
        if (kt < 7) { CP_WAIT(1); } else { CP_WAIT(0); }
        __syncthreads();

        uint32_t bufb = sb + (uint32_t)(kt & 1) * BUFB;
        uint32_t aP = bufb + aOff;
        uint32_t bP = bufb + ATILE * 2 + bOff;

        #pragma unroll
        for (int kk = 0; kk < 2; kk++) {
            uint32_t ksb = (uint32_t)(kk * 32);
            uint32_t ah[2][4];
            #pragma unroll
            for (int mt = 0; mt < 2; mt++)
                ldm_x4(ah[mt], aP + (uint32_t)(mt * 16 * SA * 2) + ksb);
            #pragma unroll
            for (int p = 0; p < 4; p++) {
                uint32_t bh[4];
                ldm_x4(bh, bP + (uint32_t)(p * 16 * SA * 2) + ksb);
                #pragma unroll
                for (int sub = 0; sub < 2; sub++) {
                    int nt = p * 2 + sub;
                    #pragma unroll
                    for (int mt = 0; mt < 2; mt++)
                        mma_f16(acc[mt][nt], ah[mt], bh[2 * sub], bh[2 * sub + 1]);
                }
            }
        }
        __syncthreads();
    }

    // ---- epilogue: write h fp16 + fused el/er ----
    int head = blockIdx.y * 2 + wn;
    float2 alv[8], arv[8];
    #pragma unroll
    for (int nt = 0; nt < 8; nt++) {
        int d = nt * 8 + 2 * t;
        alv[nt] = *(const float2*)(al + head * 64 + d);
        arv[nt] = *(const float2*)(ar + head * 64 + d);
    }

    #pragma unroll
    for (int mt = 0; mt < 2; mt++) {
        int r0 = rowBase + wm * 32 + mt * 16 + g;
        int r1 = r0 + 8;
        float el0 = 0.f, er0 = 0.f, el1 = 0.f, er1 = 0.f;
        #pragma unroll
        for (int nt = 0; nt < 8; nt++) {
            int col = nbase + wn * 64 + nt * 8 + 2 * t;
            if (r0 < nrows)
                *(__half2*)(hh_out + (size_t)r0 * 256 + col) =
                    __floats2half2_rn(acc[mt][nt][0], acc[mt][nt][1]);
            if (r1 < nrows)
                *(__half2*)(hh_out + (size_t)r1 * 256 + col) =
                    __floats2half2_rn(acc[mt][nt][2], acc[mt][nt][3]);
            el0 += acc[mt][nt][0] * alv[nt].x + acc[mt][nt][1] * alv[nt].y;
            er0 += acc[mt][nt][0] * arv[nt].x + acc[mt][nt][1] * arv[nt].y;
            el1 += acc[mt][nt][2] * alv[nt].x + acc[mt][nt][3] * alv[nt].y;
            er1 += acc[mt][nt][2] * arv[nt].x + acc[mt][nt][3] * arv[nt].y;
        }
        #pragma unroll
        for (int o = 1; o < 4; o <<= 1) {
            el0 += __shfl_xor_sync(0xffffffffu, el0, o);
            er0 += __shfl_xor_sync(0xffffffffu, er0, o);
            el1 += __shfl_xor_sync(0xffffffffu, el1, o);
            er1 += __shfl_xor_sync(0xffffffffu, er1, o);
        }
        if (t == 0) {
            if (r0 < nrows) { el_out[r0 * 4 + head] = el0; er_out[r0 * 4 + head] = er0; }
            if (r1 < nrows) { el_out[r1 * 4 + head] = el1; er_out[r1 * 4 + head] = er1; }
        }
    }
}

// ---------- warp-per-node edge-softmax + aggregation (16B/lane gathers) ------
__global__ __launch_bounds__(256) void aggregate_kernel(
    const __half* __restrict__ hh, const float* __restrict__ el,
    const float* __restrict__ er, const float* __restrict__ bias,
    float* __restrict__ outf, int write_f16, int nodeOff)
{
    __shared__ float s_w[8][32][4];
    __shared__ int   s_s[8][32];
    int w = threadIdx.x >> 5, lane = threadIdx.x & 31;
    int n = nodeOff + blockIdx.x * 8 + w;
    int beg = g_off[n], end = g_off[n + 1];
    int head = lane >> 3;

    float4 rn = ((const float4*)er)[n];
    float acc[8];
    #pragma unroll
    for (int k = 0; k < 8; k++) acc[k] = 0.f;
    float den = 0.f;
    const __half* htab = hh + (size_t)lane * 8;

    for (int base = beg; base < end; base += 32) {
        int m = end - base;
        if (m > 32) m = 32;
        if (lane < m) {
            int s = g_csrc[base + lane];
            float4 l = ((const float4*)el)[s];
            float4 wv;
            float e0 = l.x + rn.x; e0 = (e0 > 0.f) ? e0 : 0.2f * e0; wv.x = __expf(e0);
            float e1 = l.y + rn.y; e1 = (e1 > 0.f) ? e1 : 0.2f * e1; wv.y = __expf(e1);
            float e2 = l.z + rn.z; e2 = (e2 > 0.f) ? e2 : 0.2f * e2; wv.z = __expf(e2);
            float e3 = l.w + rn.w; e3 = (e3 > 0.f) ? e3 : 0.2f * e3; wv.w = __expf(e3);
            s_s[w][lane] = s;
            *(float4*)&s_w[w][lane][0] = wv;
        }
        __syncwarp();
        int j = 0;
        for (; j + 4 <= m; j += 4) {
            int   s0 = s_s[w][j],     s1 = s_s[w][j + 1];
            int   s2 = s_s[w][j + 2], s3 = s_s[w][j + 3];
            float a0 = s_w[w][j][head],     a1 = s_w[w][j + 1][head];
            float a2 = s_w[w][j + 2][head], a3 = s_w[w][j + 3][head];
            uint4 h0 = *(const uint4*)(htab + (size_t)s0 * 256);
            uint4 h1 = *(const uint4*)(htab + (size_t)s1 * 256);
            uint4 h2 = *(const uint4*)(htab + (size_t)s2 * 256);
            uint4 h3 = *(const uint4*)(htab + (size_t)s3 * 256);
            #define ACC4(hv, a)                                                   \
            do {                                                                  \
                float2 f0 = __half22float2(*(const __half2*)&(hv).x);             \
                float2 f1 = __half22float2(*(const __half2*)&(hv).y);             \
                float2 f2 = __half22float2(*(const __half2*)&(hv).z);             \
                float2 f3 = __half22float2(*(const __half2*)&(hv).w);             \
                acc[0] += (a) * f0.x; acc[1] += (a) * f0.y;                       \
                acc[2] += (a) * f1.x; acc[3] += (a) * f1.y;                       \
                acc[4] += (a) * f2.x; acc[5] += (a) * f2.y;                       \
                acc[6] += (a) * f3.x; acc[7] += (a) * f3.y;                       \
            } while (0)
            ACC4(h0, a0);
            ACC4(h1, a1);
            ACC4(h2, a2);
            ACC4(h3, a3);
            den += (a0 + a1) + (a2 + a3);
        }
        for (; j < m; j++) {
            int s0 = s_s[w][j];
            float a0 = s_w[w][j][head];
            uint4 h0 = *(const uint4*)(htab + (size_t)s0 * 256);
            ACC4(h0, a0);
            den += a0;
        }
        __syncwarp();
    }

    float inv = 1.f / den;
    float4 b0 = *(const float4*)(bias + lane * 8);
    float4 b1 = *(const float4*)(bias + lane * 8 + 4);
    float v[8];
    v[0] = fmaxf(acc[0] * inv + b0.x, 0.f);
    v[1] = fmaxf(acc[1] * inv + b0.y, 0.f);
    v[2] = fmaxf(acc[2] * inv + b0.z, 0.f);
    v[3] = fmaxf(acc[3] * inv + b0.w, 0.f);
    v[4] = fmaxf(acc[4] * inv + b1.x, 0.f);
    v[5] = fmaxf(acc[5] * inv + b1.y, 0.f);
    v[6] = fmaxf(acc[6] * inv + b1.z, 0.f);
    v[7] = fmaxf(acc[7] * inv + b1.w, 0.f);
    size_t oi = (size_t)n * 256 + lane * 8;
    if (write_f16) {
        uint4 pk;
        *(__half2*)&pk.x = __floats2half2_rn(v[0], v[1]);
        *(__half2*)&pk.y = __floats2half2_rn(v[2], v[3]);
        *(__half2*)&pk.z = __floats2half2_rn(v[4], v[5]);
        *(__half2*)&pk.w = __floats2half2_rn(v[6], v[7]);
        *(uint4*)(g_Ah + oi) = pk;
    } else {
        *(float4*)(outf + oi) = make_float4(v[0], v[1], v[2], v[3]);
        *(float4*)(outf + oi + 4) = make_float4(v[4], v[5], v[6], v[7]);
    }
}

// ---------------- launch ----------------
extern "C" void kernel_launch(void* const* d_in, const int* in_sizes, int n_in,
                              void* d_out, int out_size)
{
    const float* feat = (const float*)d_in[0];
    const int*   src  = (const int*)d_in[1];
    const int*   dst  = (const int*)d_in[2];
    const float* W1   = (const float*)d_in[3];
    const float* al1  = (const float*)d_in[4];
    const float* ar1  = (const float*)d_in[5];
    const float* b1   = (const float*)d_in[6];
    const float* W2   = (const float*)d_in[7];
    const float* al2  = (const float*)d_in[8];
    const float* ar2  = (const float*)d_in[9];
    const float* b2   = (const float*)d_in[10];
    float* out = (float*)d_out;
    int E = in_sizes[1];

    void* p;
    cudaGetSymbolAddress(&p, g_Ah);  __half* ah  = (__half*)p;
    cudaGetSymbolAddress(&p, g_Wt1); __half* wt1 = (__half*)p;
    cudaGetSymbolAddress(&p, g_Wt2); __half* wt2 = (__half*)p;
    cudaGetSymbolAddress(&p, g_hh1); __half* hh1 = (__half*)p;
    cudaGetSymbolAddress(&p, g_hh2); __half* hh2 = (__half*)p;
    cudaGetSymbolAddress(&p, g_el1); float* el1 = (float*)p;
    cudaGetSymbolAddress(&p, g_er1); float* er1 = (float*)p;
    cudaGetSymbolAddress(&p, g_el2); float* el2 = (float*)p;
    cudaGetSymbolAddress(&p, g_er2); float* er2 = (float*)p;

    static cudaStream_t s2 = nullptr, s3 = nullptr;
    static cudaEvent_t evFork = nullptr, evJoin = nullptr;
    static cudaEvent_t evG1 = nullptr, evB = nullptr, evAsb = nullptr;
    static int init_done = 0;
    if (!init_done) {
        cudaFuncSetAttribute(gemm_mma_kernel,
                             cudaFuncAttributeMaxDynamicSharedMemorySize, GEMM_SMEM);
        cudaStreamCreateWithFlags(&s2, cudaStreamNonBlocking);
        cudaStreamCreateWithFlags(&s3, cudaStreamNonBlocking);
        cudaEventCreateWithFlags(&evFork, cudaEventDisableTiming);
        cudaEventCreateWithFlags(&evJoin, cudaEventDisableTiming);
        cudaEventCreateWithFlags(&evG1, cudaEventDisableTiming);
        cudaEventCreateWithFlags(&evB, cudaEventDisableTiming);
        cudaEventCreateWithFlags(&evAsb, cudaEventDisableTiming);
        init_done = 1;
    }

    int egrid = (E + 255) / 256;
    int ngrid = (NN + 255) / 256;
    dim3 gfull((NN + 127) / 128, 2);            // 391 x 2
    dim3 ga(SPLIT / 128, 2);                    // 130 x 2
    dim3 gb((NN - SPLIT + 127) / 128, 2);       // 261 x 2 (bounds-checked)
    const int ASPLIT_A = SPLIT * 256 / 512;     // 8320
    const int ASPLIT_B = (NN - SPLIT) * 256 / 512; // 16680

    cudaEventRecord(evFork, 0);
    // s2: CSR build (overlaps splits + GEMM-1)
    cudaStreamWaitEvent(s2, evFork, 0);
    zero_indeg_kernel<<<ngrid, 256, 0, s2>>>();
    csr_count_kernel<<<egrid, 256, 0, s2>>>(dst, E);
    scan_kernel<<<1, 1024, 0, s2>>>();
    csr_scatter_kernel<<<egrid, 256, 0, s2>>>(dst, src, E);
    cudaEventRecord(evJoin, s2);

    // s3: second chunk of feature convert
    cudaStreamWaitEvent(s3, evFork, 0);
    asplit_kernel<<<ASPLIT_B, 256, 0, s3>>>(feat, (size_t)SPLIT * 256);
    cudaEventRecord(evAsb, s3);

    // s0: weight tables + first chunk convert + GEMM-1 (full)
    wsplit_kernel<<<256, 256>>>(W1, wt1);
    wsplit_kernel<<<256, 256>>>(W2, wt2);
    asplit_kernel<<<ASPLIT_A, 256>>>(feat, 0);
    cudaStreamWaitEvent(0, evAsb, 0);
    gemm_mma_kernel<<<gfull, 256, GEMM_SMEM>>>(ah, wt1, al1, ar1,
                                               hh1, el1, er1, 0, NN);
    cudaEventRecord(evG1, 0);

    // s2: agg1b (nodes >= SPLIT) after CSR (in-stream) + GEMM-1
    cudaStreamWaitEvent(s2, evG1, 0);
    aggregate_kernel<<<(NN - SPLIT) / 8, 256, 0, s2>>>(
        hh1, el1, er1, b1, nullptr, 1, SPLIT);
    cudaEventRecord(evB, s2);

    // s0: agg1a (1/3 of nodes) then gemm2a — both overlap agg1b on s2
    cudaStreamWaitEvent(0, evJoin, 0);
    aggregate_kernel<<<SPLIT / 8, 256>>>(hh1, el1, er1, b1, nullptr, 1, 0);
    gemm_mma_kernel<<<ga, 256, GEMM_SMEM>>>(ah, wt2, al2, ar2,
                                            hh2, el2, er2, 0, NN);
    // s0: gemm2b after agg1b, then final aggregate
    cudaStreamWaitEvent(0, evB, 0);
    gemm_mma_kernel<<<gb, 256, GEMM_SMEM>>>(ah, wt2, al2, ar2,
                                            hh2, el2, er2, SPLIT, NN);
    aggregate_kernel<<<NN / 8, 256>>>(hh2, el2, er2, b2, out, 0, 0);
}